// round 2
// baseline (speedup 1.0000x reference)
#include <cuda_runtime.h>
#include <math.h>

#define T_STEPS 20
#define N_NODES 32768
#define TILE_N  64
#define DH      128
#define K_TOT   192          // 64 emb + 128 hidden
#define XSTRIDE 68           // floats per X row (16B-aligned float4 rows, conflict-reduced)
#define NBLOCKS (N_NODES / TILE_N)
#define NTHREADS 256

// Pre-packed weights: g_Wc4[k*128 + j] = {W(k, j), W(k,128+j), W(k,256+j), W(k,384+j)}
// rows 0..63 from W_ih, rows 64..191 from W_hh. Combined bias per j (i,f,g,o).
__device__ float4 g_Wc4[K_TOT * 128];
__device__ float4 g_bias4[128];

__global__ void prep_kernel(const float* __restrict__ Wih, const float* __restrict__ bih,
                            const float* __restrict__ Whh, const float* __restrict__ bhh) {
    int idx = blockIdx.x * blockDim.x + threadIdx.x;
    if (idx < K_TOT * 128) {
        int k = idx >> 7;
        int j = idx & 127;
        float4 w;
        if (k < 64) {
            const float* r = Wih + k * 512;
            w = make_float4(r[j], r[128 + j], r[256 + j], r[384 + j]);
        } else {
            const float* r = Whh + (k - 64) * 512;
            w = make_float4(r[j], r[128 + j], r[256 + j], r[384 + j]);
        }
        g_Wc4[idx] = w;
    }
    if (idx < 128) {
        g_bias4[idx] = make_float4(bih[idx]       + bhh[idx],
                                   bih[128 + idx] + bhh[128 + idx],
                                   bih[256 + idx] + bhh[256 + idx],
                                   bih[384 + idx] + bhh[384 + idx]);
    }
}

__device__ __forceinline__ float sigm(float x) {
    return __fdividef(1.0f, 1.0f + __expf(-x));
}
__device__ __forceinline__ float tanh_fast(float x) {
    return __fdividef(2.0f, 1.0f + __expf(-2.0f * x)) - 1.0f;
}

#define DOQ(q, xv) \
    ai[4*q+0] = fmaf(w.x, xv.x, ai[4*q+0]); \
    ai[4*q+1] = fmaf(w.x, xv.y, ai[4*q+1]); \
    ai[4*q+2] = fmaf(w.x, xv.z, ai[4*q+2]); \
    ai[4*q+3] = fmaf(w.x, xv.w, ai[4*q+3]); \
    af[4*q+0] = fmaf(w.y, xv.x, af[4*q+0]); \
    af[4*q+1] = fmaf(w.y, xv.y, af[4*q+1]); \
    af[4*q+2] = fmaf(w.y, xv.z, af[4*q+2]); \
    af[4*q+3] = fmaf(w.y, xv.w, af[4*q+3]); \
    ag[4*q+0] = fmaf(w.z, xv.x, ag[4*q+0]); \
    ag[4*q+1] = fmaf(w.z, xv.y, ag[4*q+1]); \
    ag[4*q+2] = fmaf(w.z, xv.z, ag[4*q+2]); \
    ag[4*q+3] = fmaf(w.z, xv.w, ag[4*q+3]); \
    ao[4*q+0] = fmaf(w.w, xv.x, ao[4*q+0]); \
    ao[4*q+1] = fmaf(w.w, xv.y, ao[4*q+1]); \
    ao[4*q+2] = fmaf(w.w, xv.z, ao[4*q+2]); \
    ao[4*q+3] = fmaf(w.w, xv.w, ao[4*q+3]);

__global__ __launch_bounds__(NTHREADS, 1)
void vlstm_kernel(const float* __restrict__ nodes,
                  const int* __restrict__ mask,      // bool widened to int32 by harness
                  const float* __restrict__ h0,
                  const float* __restrict__ c0,
                  const float* __restrict__ We,
                  const float* __restrict__ be,
                  const float* __restrict__ Wout,
                  const float* __restrict__ bout,
                  float* __restrict__ out,      // [T, N, 5]
                  float* __restrict__ hfin,     // [N, 128]
                  float* __restrict__ cfin) {   // [N, 128]
    extern __shared__ float smem[];
    float* sh = smem;                     // [TILE_N][128]
    float* sc = smem + TILE_N * DH;       // [TILE_N][128]
    float* sX = smem + 2 * TILE_N * DH;   // [K_TOT][XSTRIDE]
    int* sActive = (int*)(sX + K_TOT * XSTRIDE);  // [64]
    int* sMaskA  = sActive + TILE_N;               // [64]
    int* sCnt    = sMaskA + TILE_N;                // [2] = {count, pad}

    const int tid  = threadIdx.x;
    const int base = blockIdx.x * TILE_N;
    const int cs   = tid >> 7;    // chunk-set 0/1
    const int j    = tid & 127;   // hidden unit owned by this thread

    // Load initial h, c
    for (int idx = tid; idx < TILE_N * DH; idx += NTHREADS) {
        sh[idx] = h0[base * DH + idx];
        sc[idx] = c0[base * DH + idx];
    }
    const float4 bias = g_bias4[j];
    __syncthreads();

    for (int t = 0; t < T_STEPS; t++) {
        // ---- active-node compaction (one warp) ----
        if (tid < 32) {
            const int* mrow = mask + (size_t)t * N_NODES + base;
            int m0 = mrow[tid]       != 0;
            int m1 = mrow[32 + tid]  != 0;
            sMaskA[tid]      = m0;
            sMaskA[32 + tid] = m1;
            unsigned lt = (1u << tid) - 1u;
            unsigned b0 = __ballot_sync(0xffffffffu, m0);
            int c0n = __popc(b0);
            if (m0) sActive[__popc(b0 & lt)] = tid;
            unsigned b1 = __ballot_sync(0xffffffffu, m1);
            if (m1) sActive[c0n + __popc(b1 & lt)] = 32 + tid;
            int cnt = c0n + __popc(b1);
            int pad = (cnt + 15) & ~15;
            __syncwarp();
            int dup = (cnt > 0) ? sActive[0] : 0;
            for (int p = cnt + tid; p < pad; p += 32) sActive[p] = dup;
            if (tid == 0) { sCnt[0] = cnt; sCnt[1] = pad; }
        }
        __syncthreads();
        const int cnt = sCnt[0];
        const int pad = sCnt[1];
        const int nch = pad >> 4;

        // ---- build X = [relu(x @ We + be) ; h] for padded active slots ----
        for (int idx = tid; idx < pad * 64; idx += NTHREADS) {
            int a = idx >> 6, k = idx & 63;
            int n = base + sActive[a];
            float x0 = nodes[((size_t)t * N_NODES + n) * 2];
            float x1 = nodes[((size_t)t * N_NODES + n) * 2 + 1];
            float e = fmaf(x0, We[k], fmaf(x1, We[64 + k], be[k]));
            sX[k * XSTRIDE + a] = fmaxf(e, 0.0f);
        }
        for (int idx = tid; idx < pad * DH; idx += NTHREADS) {
            int a = idx >> 7, k = idx & 127;
            sX[(64 + k) * XSTRIDE + a] = sh[sActive[a] * DH + k];
        }
        __syncthreads();

        // ---- GEMM + fused LSTM cell: thread owns unit j, 16 nodes per chunk ----
        for (int chunk = cs; chunk < nch; chunk += 2) {
            const int a0 = chunk * 16;
            float ai[16], af[16], ag[16], ao[16];
            #pragma unroll
            for (int m = 0; m < 16; m++) {
                ai[m] = bias.x; af[m] = bias.y; ag[m] = bias.z; ao[m] = bias.w;
            }
            const float4* Wp = g_Wc4 + j;
            const float*  Xp = sX + a0;
            #pragma unroll 4
            for (int k = 0; k < K_TOT; k++) {
                float4 w = Wp[k * 128];
                const float4* xr = (const float4*)(Xp + k * XSTRIDE);
                float4 x0 = xr[0];
                float4 x1 = xr[1];
                float4 x2 = xr[2];
                float4 x3 = xr[3];
                DOQ(0, x0)
                DOQ(1, x1)
                DOQ(2, x2)
                DOQ(3, x3)
            }
            #pragma unroll
            for (int m = 0; m < 16; m++) {
                if (a0 + m < cnt) {    // skip padded duplicates (avoid double-update race)
                    int n = sActive[a0 + m];
                    float ig = sigm(ai[m]);
                    float fg = sigm(af[m]);
                    float gg = tanh_fast(ag[m]);
                    float og = sigm(ao[m]);
                    float cn = fmaf(fg, sc[n * DH + j], ig * gg);
                    float hn = og * tanh_fast(cn);
                    sc[n * DH + j] = cn;
                    sh[n * DH + j] = hn;
                }
            }
        }
        __syncthreads();

        // ---- outputs: active nodes get h_new @ W_out + b_out ----
        {
            int warp = tid >> 5, lane = tid & 31;
            for (int a = warp; a < cnt; a += 8) {
                int n = sActive[a];
                float o0 = 0.f, o1 = 0.f, o2 = 0.f, o3 = 0.f, o4 = 0.f;
                #pragma unroll
                for (int q = 0; q < 4; q++) {
                    int jj = lane + q * 32;
                    float hv = sh[n * DH + jj];
                    const float* wr = Wout + jj * 5;
                    o0 = fmaf(hv, wr[0], o0);
                    o1 = fmaf(hv, wr[1], o1);
                    o2 = fmaf(hv, wr[2], o2);
                    o3 = fmaf(hv, wr[3], o3);
                    o4 = fmaf(hv, wr[4], o4);
                }
                #pragma unroll
                for (int off = 16; off > 0; off >>= 1) {
                    o0 += __shfl_down_sync(0xffffffffu, o0, off);
                    o1 += __shfl_down_sync(0xffffffffu, o1, off);
                    o2 += __shfl_down_sync(0xffffffffu, o2, off);
                    o3 += __shfl_down_sync(0xffffffffu, o3, off);
                    o4 += __shfl_down_sync(0xffffffffu, o4, off);
                }
                if (lane == 0) {
                    float* op = out + ((size_t)t * N_NODES + base + n) * 5;
                    op[0] = o0 + bout[0];
                    op[1] = o1 + bout[1];
                    op[2] = o2 + bout[2];
                    op[3] = o3 + bout[3];
                    op[4] = o4 + bout[4];
                }
            }
        }
        // ---- inactive nodes output zeros ----
        if (tid < TILE_N) {
            if (!sMaskA[tid]) {
                float* op = out + ((size_t)t * N_NODES + base + tid) * 5;
                op[0] = 0.f; op[1] = 0.f; op[2] = 0.f; op[3] = 0.f; op[4] = 0.f;
            }
        }
        __syncthreads();
    }

    // ---- final h, c ----
    for (int idx = tid; idx < TILE_N * DH; idx += NTHREADS) {
        hfin[base * DH + idx] = sh[idx];
        cfin[base * DH + idx] = sc[idx];
    }
}

extern "C" void kernel_launch(void* const* d_in, const int* in_sizes, int n_in,
                              void* d_out, int out_size) {
    const float* nodes = (const float*)d_in[0];
    const int* mask    = (const int*)d_in[1];     // bool -> int32
    const float* h0    = (const float*)d_in[2];
    const float* c0    = (const float*)d_in[3];
    const float* We    = (const float*)d_in[4];
    const float* be    = (const float*)d_in[5];
    const float* Wih   = (const float*)d_in[6];
    const float* bih   = (const float*)d_in[7];
    const float* Whh   = (const float*)d_in[8];
    const float* bhh   = (const float*)d_in[9];
    const float* Wout  = (const float*)d_in[10];
    const float* bout  = (const float*)d_in[11];

    float* out  = (float*)d_out;                            // [20, 32768, 5]
    float* hfin = out + (size_t)T_STEPS * N_NODES * 5;      // [32768, 128]
    float* cfin = hfin + (size_t)N_NODES * DH;              // [32768, 128]

    // Pack weights (cheap, re-done each launch; deterministic)
    prep_kernel<<<(K_TOT * 128 + 255) / 256, 256>>>(Wih, bih, Whh, bhh);

    const int smem_bytes = (2 * TILE_N * DH + K_TOT * XSTRIDE) * 4 + (TILE_N * 2 + 2) * 4;
    cudaFuncSetAttribute(vlstm_kernel, cudaFuncAttributeMaxDynamicSharedMemorySize,
                         smem_bytes);
    vlstm_kernel<<<NBLOCKS, NTHREADS, smem_bytes>>>(
        nodes, mask, h0, c0, We, be, Wout, bout, out, hfin, cfin);
}

// round 3
// speedup vs baseline: 1.3273x; 1.3273x over previous
#include <cuda_runtime.h>
#include <math.h>

#define T_STEPS 20
#define N_NODES 32768
#define TILE_N  64
#define DH      128
#define K_TOT   192          // 64 emb + 128 hidden
#define XSTRIDE 36           // floats per X row (16B-aligned, 32-node groups)
#define NBLOCKS (N_NODES / TILE_N)
#define NTHREADS 256

// Pre-packed weights: g_Wc4[k*128 + j] = {W(k, j), W(k,128+j), W(k,256+j), W(k,384+j)}
// rows 0..63 from W_ih, rows 64..191 from W_hh. Combined bias per j (i,f,g,o).
__device__ float4 g_Wc4[K_TOT * 128];
__device__ float4 g_bias4[128];

__global__ void prep_kernel(const float* __restrict__ Wih, const float* __restrict__ bih,
                            const float* __restrict__ Whh, const float* __restrict__ bhh) {
    int idx = blockIdx.x * blockDim.x + threadIdx.x;
    if (idx < K_TOT * 128) {
        int k = idx >> 7;
        int j = idx & 127;
        float4 w;
        if (k < 64) {
            const float* r = Wih + k * 512;
            w = make_float4(r[j], r[128 + j], r[256 + j], r[384 + j]);
        } else {
            const float* r = Whh + (k - 64) * 512;
            w = make_float4(r[j], r[128 + j], r[256 + j], r[384 + j]);
        }
        g_Wc4[idx] = w;
    }
    if (idx < 128) {
        g_bias4[idx] = make_float4(bih[idx]       + bhh[idx],
                                   bih[128 + idx] + bhh[128 + idx],
                                   bih[256 + idx] + bhh[256 + idx],
                                   bih[384 + idx] + bhh[384 + idx]);
    }
}

__device__ __forceinline__ float tanh_apx(float x) {
    float y;
    asm("tanh.approx.f32 %0, %1;" : "=f"(y) : "f"(x));
    return y;
}
__device__ __forceinline__ float sigm(float x) {
    return fmaf(0.5f, tanh_apx(0.5f * x), 0.5f);
}

#define DOQ(q, xv) \
    ai[4*q+0] = fmaf(w.x, xv.x, ai[4*q+0]); \
    ai[4*q+1] = fmaf(w.x, xv.y, ai[4*q+1]); \
    ai[4*q+2] = fmaf(w.x, xv.z, ai[4*q+2]); \
    ai[4*q+3] = fmaf(w.x, xv.w, ai[4*q+3]); \
    af[4*q+0] = fmaf(w.y, xv.x, af[4*q+0]); \
    af[4*q+1] = fmaf(w.y, xv.y, af[4*q+1]); \
    af[4*q+2] = fmaf(w.y, xv.z, af[4*q+2]); \
    af[4*q+3] = fmaf(w.y, xv.w, af[4*q+3]); \
    ag[4*q+0] = fmaf(w.z, xv.x, ag[4*q+0]); \
    ag[4*q+1] = fmaf(w.z, xv.y, ag[4*q+1]); \
    ag[4*q+2] = fmaf(w.z, xv.z, ag[4*q+2]); \
    ag[4*q+3] = fmaf(w.z, xv.w, ag[4*q+3]); \
    ao[4*q+0] = fmaf(w.w, xv.x, ao[4*q+0]); \
    ao[4*q+1] = fmaf(w.w, xv.y, ao[4*q+1]); \
    ao[4*q+2] = fmaf(w.w, xv.z, ao[4*q+2]); \
    ao[4*q+3] = fmaf(w.w, xv.w, ao[4*q+3]);

__global__ __launch_bounds__(NTHREADS, 2)
void vlstm_kernel(const float* __restrict__ nodes,
                  const int* __restrict__ mask,      // bool widened to int32
                  const float* __restrict__ h0,
                  const float* __restrict__ c0,
                  const float* __restrict__ We,
                  const float* __restrict__ be,
                  const float* __restrict__ Wout,
                  const float* __restrict__ bout,
                  float* __restrict__ out,      // [T, N, 5]
                  float* __restrict__ hfin,     // [N, 128]
                  float* __restrict__ cfin) {   // [N, 128]
    extern __shared__ float smem[];
    float*  sh      = smem;                         // [64][128]
    float*  sc      = sh + TILE_N * DH;             // [64][128]
    float*  sX      = sc + TILE_N * DH;             // [192][36]
    float2* sXY     = (float2*)(sX + K_TOT * XSTRIDE);  // [64]
    float*  sWe     = (float*)(sXY + TILE_N);       // [128]
    float*  sBe     = sWe + 128;                    // [64]
    float*  sWout   = sBe + 64;                     // [640]
    float*  sBout   = sWout + 640;                  // [8]
    int*    sActive = (int*)(sBout + 8);            // [64]
    int*    sMaskA  = sActive + TILE_N;             // [64]
    int*    sCnt    = sMaskA + TILE_N;              // [2]

    const int tid  = threadIdx.x;
    const int base = blockIdx.x * TILE_N;
    const int cs   = tid >> 7;    // chunk-set 0/1
    const int j    = tid & 127;   // hidden unit owned by this thread

    // Stage constants + initial h, c
    for (int idx = tid; idx < TILE_N * DH; idx += NTHREADS) {
        sh[idx] = h0[base * DH + idx];
        sc[idx] = c0[base * DH + idx];
    }
    if (tid < 128) sWe[tid] = We[tid];
    if (tid >= 128 && tid < 192) sBe[tid - 128] = be[tid - 128];
    for (int idx = tid; idx < 640; idx += NTHREADS) sWout[idx] = Wout[idx];
    if (tid >= 192 && tid < 197) sBout[tid - 192] = bout[tid - 192];
    const float4 bias = g_bias4[j];
    __syncthreads();

    for (int t = 0; t < T_STEPS; t++) {
        // ---- active-node compaction (one warp) ----
        if (tid < 32) {
            const int* mrow = mask + (size_t)t * N_NODES + base;
            int m0 = mrow[tid]       != 0;
            int m1 = mrow[32 + tid]  != 0;
            sMaskA[tid]      = m0;
            sMaskA[32 + tid] = m1;
            unsigned lt = (1u << tid) - 1u;
            unsigned b0 = __ballot_sync(0xffffffffu, m0);
            int c0n = __popc(b0);
            if (m0) sActive[__popc(b0 & lt)] = tid;
            unsigned b1 = __ballot_sync(0xffffffffu, m1);
            if (m1) sActive[c0n + __popc(b1 & lt)] = 32 + tid;
            int cnt = c0n + __popc(b1);
            int pad = (cnt + 15) & ~15;
            __syncwarp();
            int dup = (cnt > 0) ? sActive[0] : 0;
            for (int p = cnt + tid; p < pad; p += 32) sActive[p] = dup;
            if (tid == 0) { sCnt[0] = cnt; sCnt[1] = pad; }
        }
        __syncthreads();
        const int cnt = sCnt[0];
        const int pad = sCnt[1];

        // ---- stage (x0,x1) pairs for padded active slots ----
        if (tid < pad) {
            int n = base + sActive[tid];
            sXY[tid] = ((const float2*)nodes)[(size_t)t * N_NODES + n];
        }
        __syncthreads();

        // ---- process active nodes in groups of <=32 ----
        for (int g0 = 0; g0 < pad; g0 += 32) {
            const int gpad = min(pad - g0, 32);

            // build X = [relu(x @ We + be) ; h] for this group
            for (int idx = tid; idx < gpad * 64; idx += NTHREADS) {
                int a = idx >> 6, k = idx & 63;
                float2 xy = sXY[g0 + a];
                float e = fmaf(xy.x, sWe[k], fmaf(xy.y, sWe[64 + k], sBe[k]));
                sX[k * XSTRIDE + a] = fmaxf(e, 0.0f);
            }
            for (int idx = tid; idx < gpad * DH; idx += NTHREADS) {
                int a = idx >> 7, k = idx & 127;
                sX[(64 + k) * XSTRIDE + a] = sh[sActive[g0 + a] * DH + k];
            }
            __syncthreads();

            // GEMM + fused LSTM cell: thread owns unit j, 16 nodes per chunk
            const int a0 = cs * 16;
            if (a0 < gpad) {
                float ai[16], af[16], ag[16], ao[16];
                #pragma unroll
                for (int m = 0; m < 16; m++) {
                    ai[m] = bias.x; af[m] = bias.y; ag[m] = bias.z; ao[m] = bias.w;
                }
                const float4* Wp = g_Wc4 + j;
                const float*  Xp = sX + a0;
                // distance-2 software pipeline on the weight row
                float4 wbuf0 = Wp[0];
                float4 wbuf1 = Wp[128];
                #pragma unroll 2
                for (int k = 0; k < K_TOT; k++) {
                    float4 w = (k & 1) ? wbuf1 : wbuf0;
                    if (k + 2 < K_TOT) {
                        float4 wn = Wp[(k + 2) * 128];
                        if (k & 1) wbuf1 = wn; else wbuf0 = wn;
                    }
                    const float4* xr = (const float4*)(Xp + k * XSTRIDE);
                    float4 x0 = xr[0];
                    float4 x1 = xr[1];
                    DOQ(0, x0)
                    DOQ(1, x1)
                    float4 x2 = xr[2];
                    float4 x3 = xr[3];
                    DOQ(2, x2)
                    DOQ(3, x3)
                }
                #pragma unroll
                for (int m = 0; m < 16; m++) {
                    if (g0 + a0 + m < cnt) {
                        int n = sActive[g0 + a0 + m];
                        float ig = sigm(ai[m]);
                        float fg = sigm(af[m]);
                        float gg = tanh_apx(ag[m]);
                        float og = sigm(ao[m]);
                        float cn = fmaf(fg, sc[n * DH + j], ig * gg);
                        float hn = og * tanh_apx(cn);
                        sc[n * DH + j] = cn;
                        sh[n * DH + j] = hn;
                    }
                }
            }
            __syncthreads();
        }

        // ---- outputs: active nodes get h_new @ W_out + b_out ----
        {
            int warp = tid >> 5, lane = tid & 31;
            for (int a = warp; a < cnt; a += 8) {
                int n = sActive[a];
                float o0 = 0.f, o1 = 0.f, o2 = 0.f, o3 = 0.f, o4 = 0.f;
                #pragma unroll
                for (int q = 0; q < 4; q++) {
                    int jj = lane + q * 32;
                    float hv = sh[n * DH + jj];
                    const float* wr = sWout + jj * 5;
                    o0 = fmaf(hv, wr[0], o0);
                    o1 = fmaf(hv, wr[1], o1);
                    o2 = fmaf(hv, wr[2], o2);
                    o3 = fmaf(hv, wr[3], o3);
                    o4 = fmaf(hv, wr[4], o4);
                }
                #pragma unroll
                for (int off = 16; off > 0; off >>= 1) {
                    o0 += __shfl_down_sync(0xffffffffu, o0, off);
                    o1 += __shfl_down_sync(0xffffffffu, o1, off);
                    o2 += __shfl_down_sync(0xffffffffu, o2, off);
                    o3 += __shfl_down_sync(0xffffffffu, o3, off);
                    o4 += __shfl_down_sync(0xffffffffu, o4, off);
                }
                if (lane == 0) {
                    float* op = out + ((size_t)t * N_NODES + base + n) * 5;
                    op[0] = o0 + sBout[0];
                    op[1] = o1 + sBout[1];
                    op[2] = o2 + sBout[2];
                    op[3] = o3 + sBout[3];
                    op[4] = o4 + sBout[4];
                }
            }
        }
        // ---- inactive nodes output zeros ----
        if (tid < TILE_N) {
            if (!sMaskA[tid]) {
                float* op = out + ((size_t)t * N_NODES + base + tid) * 5;
                op[0] = 0.f; op[1] = 0.f; op[2] = 0.f; op[3] = 0.f; op[4] = 0.f;
            }
        }
        __syncthreads();
    }

    // ---- final h, c ----
    for (int idx = tid; idx < TILE_N * DH; idx += NTHREADS) {
        hfin[base * DH + idx] = sh[idx];
        cfin[base * DH + idx] = sc[idx];
    }
}

extern "C" void kernel_launch(void* const* d_in, const int* in_sizes, int n_in,
                              void* d_out, int out_size) {
    const float* nodes = (const float*)d_in[0];
    const int* mask    = (const int*)d_in[1];     // bool -> int32
    const float* h0    = (const float*)d_in[2];
    const float* c0    = (const float*)d_in[3];
    const float* We    = (const float*)d_in[4];
    const float* be    = (const float*)d_in[5];
    const float* Wih   = (const float*)d_in[6];
    const float* bih   = (const float*)d_in[7];
    const float* Whh   = (const float*)d_in[8];
    const float* bhh   = (const float*)d_in[9];
    const float* Wout  = (const float*)d_in[10];
    const float* bout  = (const float*)d_in[11];

    float* out  = (float*)d_out;                            // [20, 32768, 5]
    float* hfin = out + (size_t)T_STEPS * N_NODES * 5;      // [32768, 128]
    float* cfin = hfin + (size_t)N_NODES * DH;              // [32768, 128]

    prep_kernel<<<(K_TOT * 128 + 255) / 256, 256>>>(Wih, bih, Whh, bhh);

    const int smem_floats = 2 * TILE_N * DH       // sh, sc
                          + K_TOT * XSTRIDE       // sX
                          + TILE_N * 2            // sXY
                          + 128 + 64              // sWe, sBe
                          + 640 + 8               // sWout, sBout
                          + TILE_N * 2 + 2;       // sActive, sMaskA, sCnt
    const int smem_bytes = smem_floats * 4;
    cudaFuncSetAttribute(vlstm_kernel, cudaFuncAttributeMaxDynamicSharedMemorySize,
                         smem_bytes);
    vlstm_kernel<<<NBLOCKS, NTHREADS, smem_bytes>>>(
        nodes, mask, h0, c0, We, be, Wout, bout, out, hfin, cfin);
}

// round 6
// speedup vs baseline: 1.3482x; 1.0158x over previous
#include <cuda_runtime.h>
#include <cuda_bf16.h>
#include <cstdint>

#define T_STEPS 20
#define N_NODES 32768
#define TILE_N  128
#define DH      128
#define K_TOT   192
#define NBLOCKS (N_NODES / TILE_N)   // 256
#define NTHREADS 256
#define NCHUNKS 16                   // 512 interleaved gate cols in chunks of 32
#define XPITCH  400                  // bytes per X/W row (200 bf16, conflict-free ldmatrix)
#define WCHUNK  12800                // 32 rows * 400B

// SMEM byte offsets
#define SM_XH 0                      // X hi: 128 x 400
#define SM_XL 51200                  // X lo
#define SM_WB 102400                 // 2 bufs x (hi 12800 + lo 12800)
#define SM_HH 153600                 // h hi: 128 x 128 bf16
#define SM_HL 186368                 // h lo
#define SM_F  219136                 // float region
#define SMEM_TOTAL 226688

// ---- static device scratch ----
__device__ unsigned short g_WH[NCHUNKS * 32 * 200];   // bf16 bits, [chunk][row][200]
__device__ unsigned short g_WL[NCHUNKS * 32 * 200];
__device__ float g_C[DH * N_NODES];                   // cell state transposed [j][n]

// prep: W'[n'=j*4+g][k] = Wfull[k][g*128+j], bf16 hi/lo, pitch 200
__global__ void prep_kernel(const float* __restrict__ Wih, const float* __restrict__ Whh) {
    int idx = blockIdx.x * blockDim.x + threadIdx.x;
    if (idx >= 512 * K_TOT) return;
    int np = idx / K_TOT;
    int k  = idx % K_TOT;
    int j = np >> 2, g = np & 3;
    int col = g * 128 + j;
    float w = (k < 64) ? Wih[k * 512 + col] : Whh[(k - 64) * 512 + col];
    __nv_bfloat16 hi = __float2bfloat16(w);
    __nv_bfloat16 lo = __float2bfloat16(w - __bfloat162float(hi));
    int off = (np >> 5) * 6400 + (np & 31) * 200 + k;
    g_WH[off] = __bfloat16_as_ushort(hi);
    g_WL[off] = __bfloat16_as_ushort(lo);
}

// ---- PTX helpers (portable ISA only) ----
__device__ __forceinline__ uint32_t smem_u32(const void* p) {
    uint32_t a;
    asm("{ .reg .u64 t; cvta.to.shared.u64 t, %1; cvt.u32.u64 %0, t; }" : "=r"(a) : "l"(p));
    return a;
}
__device__ __forceinline__ void ldsm4(uint32_t& r0, uint32_t& r1, uint32_t& r2, uint32_t& r3, uint32_t addr) {
    asm volatile("ldmatrix.sync.aligned.m8n8.x4.shared.b16 {%0,%1,%2,%3}, [%4];"
                 : "=r"(r0), "=r"(r1), "=r"(r2), "=r"(r3) : "r"(addr));
}
__device__ __forceinline__ void mma16816(float* d, const uint32_t* a, const uint32_t* b) {
    asm volatile("mma.sync.aligned.m16n8k16.row.col.f32.bf16.bf16.f32 "
                 "{%0,%1,%2,%3},{%4,%5,%6,%7},{%8,%9},{%0,%1,%2,%3};"
                 : "+f"(d[0]), "+f"(d[1]), "+f"(d[2]), "+f"(d[3])
                 : "r"(a[0]), "r"(a[1]), "r"(a[2]), "r"(a[3]), "r"(b[0]), "r"(b[1]));
}
__device__ __forceinline__ void cpasync16(uint32_t dst, const void* src) {
    asm volatile("cp.async.cg.shared.global [%0], [%1], 16;" :: "r"(dst), "l"(src) : "memory");
}
#define CP_COMMIT() asm volatile("cp.async.commit_group;" ::: "memory")
#define CP_WAIT(N)  asm volatile("cp.async.wait_group %0;" :: "n"(N) : "memory")

__device__ __forceinline__ float tanh_apx(float x) {
    float y;
    asm("tanh.approx.f32 %0, %1;" : "=f"(y) : "f"(x));
    return y;
}
__device__ __forceinline__ float sigm(float x) { return fmaf(0.5f, tanh_apx(0.5f * x), 0.5f); }
__device__ __forceinline__ void bf16_split(float v, unsigned short& hi, unsigned short& lo) {
    __nv_bfloat16 h = __float2bfloat16(v);
    hi = __bfloat16_as_ushort(h);
    lo = __bfloat16_as_ushort(__float2bfloat16(v - __bfloat162float(h)));
}

__global__ __launch_bounds__(NTHREADS, 1)
void vlstm_mma(const float* __restrict__ nodes,
               const int* __restrict__ mask,
               const float* __restrict__ h0,
               const float* __restrict__ c0,
               const float* __restrict__ We,
               const float* __restrict__ be,
               const float* __restrict__ bih,
               const float* __restrict__ bhh,
               const float* __restrict__ Wout,
               const float* __restrict__ bout,
               float* __restrict__ out,
               float* __restrict__ hfin,
               float* __restrict__ cfin) {
    extern __shared__ char smem[];
    float* sBias = (float*)(smem + SM_F);   // 512
    float* sWe   = sBias + 512;             // 128
    float* sBe   = sWe + 128;               // 64
    float* sWout = sBe + 64;                // 640
    float* sBout = sWout + 640;             // 8
    float* sXY   = sBout + 8;               // 256
    int* sActive = (int*)(sXY + 256);       // 128
    int* sMask   = sActive + 128;           // 128
    int* sCnt    = sMask + 128;             // 2

    const int tid  = threadIdx.x;
    const int wid  = tid >> 5, lane = tid & 31;
    const int base = blockIdx.x * TILE_N;
    const uint32_t sbase = smem_u32(smem);

    // stage constants
    for (int i = tid; i < 512; i += NTHREADS) sBias[i] = bih[i] + bhh[i];
    for (int i = tid; i < 128; i += NTHREADS) sWe[i] = We[i];
    for (int i = tid; i < 64;  i += NTHREADS) sBe[i] = be[i];
    for (int i = tid; i < 640; i += NTHREADS) sWout[i] = Wout[i];
    if (tid < 5) sBout[tid] = bout[tid];

    // zero X buffers (garbage hygiene for padded rows)
    for (int i = tid; i < 12800; i += NTHREADS) {
        ((uint32_t*)(smem + SM_XH))[i] = 0;
        ((uint32_t*)(smem + SM_XL))[i] = 0;
    }
    // h0 -> hH/hL bf16 split; c0 -> g_C transposed
    for (int idx = tid; idx < TILE_N * 64; idx += NTHREADS) {
        int n = idx >> 6, q = idx & 63;
        float2 hv = ((const float2*)h0)[(size_t)(base + n) * 64 + q];
        unsigned short h0a, l0a, h1a, l1a;
        bf16_split(hv.x, h0a, l0a);
        bf16_split(hv.y, h1a, l1a);
        ((uint32_t*)(smem + SM_HH))[n * 64 + q] = (uint32_t)h0a | ((uint32_t)h1a << 16);
        ((uint32_t*)(smem + SM_HL))[n * 64 + q] = (uint32_t)l0a | ((uint32_t)l1a << 16);
    }
    for (int idx = tid; idx < TILE_N * DH; idx += NTHREADS) {
        int j = idx >> 7, n = idx & 127;
        g_C[(size_t)j * N_NODES + base + n] = c0[(size_t)(base + n) * DH + j];
    }
    __syncthreads();

    for (int t = 0; t < T_STEPS; t++) {
        // ---- compaction (warp 0) ----
        if (tid < 32) {
            int cnt = 0;
            #pragma unroll
            for (int g2 = 0; g2 < 4; g2++) {
                int m = mask[(size_t)t * N_NODES + base + g2 * 32 + tid] != 0;
                sMask[g2 * 32 + tid] = m;
                unsigned b = __ballot_sync(0xffffffffu, m);
                if (m) sActive[cnt + __popc(b & ((1u << tid) - 1u))] = g2 * 32 + tid;
                cnt += __popc(b);
            }
            int pad = (cnt + 15) & ~15;
            __syncwarp();
            int dup = (cnt > 0) ? sActive[0] : 0;
            for (int p = cnt + tid; p < pad; p += 32) sActive[p] = dup;
            if (tid == 0) { sCnt[0] = cnt; sCnt[1] = pad; }
        }
        __syncthreads();
        const int cnt = sCnt[0];
        const int pad = sCnt[1];

        if (pad > 0) {
            // ---- stage xy, gather h rows into X, prefetch chunk 0 ----
            if (tid < pad) {
                int n = base + sActive[tid];
                float2 xy = ((const float2*)nodes)[(size_t)t * N_NODES + n];
                sXY[2 * tid] = xy.x;
                sXY[2 * tid + 1] = xy.y;
            }
            for (int idx = tid; idx < pad * 64; idx += NTHREADS) {
                int a = idx >> 6, q = idx & 63;
                int n = sActive[a];
                *(uint32_t*)(smem + SM_XH + a * XPITCH + 128 + 4 * q) =
                    ((uint32_t*)(smem + SM_HH))[n * 64 + q];
                *(uint32_t*)(smem + SM_XL + a * XPITCH + 128 + 4 * q) =
                    ((uint32_t*)(smem + SM_HL))[n * 64 + q];
            }
            for (int i = tid * 16; i < WCHUNK; i += NTHREADS * 16) {
                cpasync16(sbase + SM_WB + i, (const char*)g_WH + i);
                cpasync16(sbase + SM_WB + WCHUNK + i, (const char*)g_WL + i);
            }
            CP_COMMIT();
            __syncthreads();

            // ---- emb rows (X cols 0..63) ----
            for (int idx = tid; idx < pad * 64; idx += NTHREADS) {
                int a = idx >> 6, k = idx & 63;
                float e = fmaxf(fmaf(sXY[2 * a], sWe[k],
                                fmaf(sXY[2 * a + 1], sWe[64 + k], sBe[k])), 0.0f);
                unsigned short hi, lo;
                bf16_split(e, hi, lo);
                *(unsigned short*)(smem + SM_XH + a * XPITCH + 2 * k) = hi;
                *(unsigned short*)(smem + SM_XL + a * XPITCH + 2 * k) = lo;
            }

            const int npairs = (pad >> 4) * 2;
            const int nh = wid & 1;
            const int mt0 = wid >> 1;          // pair p = wid
            const int mt1 = (wid >> 1) + 4;    // pair p = wid + 8
            // A-operand lane addressing
            const uint32_t aoff = (uint32_t)((lane & 7) + ((lane >> 3) & 1) * 8) * XPITCH
                                + (uint32_t)(lane >> 4) * 16;
            // B-operand lane addressing (within chunk buf)
            const uint32_t boff = (uint32_t)(nh * 16 + (lane & 7) + ((lane >> 4) & 1) * 8) * XPITCH
                                + (uint32_t)((lane >> 3) & 1) * 16;

            // ---- chunk pipeline ----
            for (int nc = 0; nc < NCHUNKS; nc++) {
                int buf = nc & 1;
                if (nc + 1 < NCHUNKS) {
                    int nbuf = (nc + 1) & 1;
                    const char* srcH = (const char*)g_WH + (nc + 1) * WCHUNK;
                    const char* srcL = (const char*)g_WL + (nc + 1) * WCHUNK;
                    uint32_t dstH = sbase + SM_WB + nbuf * 2 * WCHUNK;
                    for (int i = tid * 16; i < WCHUNK; i += NTHREADS * 16) {
                        cpasync16(dstH + i, srcH + i);
                        cpasync16(dstH + WCHUNK + i, srcL + i);
                    }
                    CP_COMMIT();
                    CP_WAIT(1);
                } else {
                    CP_WAIT(0);
                }
                __syncthreads();

                const bool act0 = (wid < npairs);
                const bool act1 = (wid + 8 < npairs);
                if (act0) {
                    float acc[2][2][4];
                    #pragma unroll
                    for (int r = 0; r < 2; r++)
                        #pragma unroll
                        for (int q = 0; q < 2; q++)
                            #pragma unroll
                            for (int z = 0; z < 4; z++) acc[r][q][z] = 0.0f;

                    const uint32_t xh = sbase + SM_XH + (uint32_t)mt0 * 16 * XPITCH + aoff;
                    const uint32_t xl = sbase + SM_XL + (uint32_t)mt0 * 16 * XPITCH + aoff;
                    const uint32_t xh1 = sbase + SM_XH + (uint32_t)mt1 * 16 * XPITCH + aoff;
                    const uint32_t xl1 = sbase + SM_XL + (uint32_t)mt1 * 16 * XPITCH + aoff;
                    const uint32_t wb = sbase + SM_WB + (uint32_t)buf * 2 * WCHUNK + boff;

                    #pragma unroll 4
                    for (int kk = 0; kk < 12; kk++) {
                        uint32_t kb = kk * 32;   // byte offset of k0*2
                        uint32_t bh[4], bl[4], ah[4], al[4];
                        ldsm4(bh[0], bh[1], bh[2], bh[3], wb + kb);
                        ldsm4(bl[0], bl[1], bl[2], bl[3], wb + WCHUNK + kb);
                        ldsm4(ah[0], ah[1], ah[2], ah[3], xh + kb);
                        ldsm4(al[0], al[1], al[2], al[3], xl + kb);
                        mma16816(acc[0][0], ah, bh + 0);
                        mma16816(acc[0][1], ah, bh + 2);
                        mma16816(acc[0][0], al, bh + 0);
                        mma16816(acc[0][1], al, bh + 2);
                        mma16816(acc[0][0], ah, bl + 0);
                        mma16816(acc[0][1], ah, bl + 2);
                        if (act1) {
                            uint32_t ah1[4], al1[4];
                            ldsm4(ah1[0], ah1[1], ah1[2], ah1[3], xh1 + kb);
                            ldsm4(al1[0], al1[1], al1[2], al1[3], xl1 + kb);
                            mma16816(acc[1][0], ah1, bh + 0);
                            mma16816(acc[1][1], ah1, bh + 2);
                            mma16816(acc[1][0], al1, bh + 0);
                            mma16816(acc[1][1], al1, bh + 2);
                            mma16816(acc[1][0], ah1, bl + 0);
                            mma16816(acc[1][1], ah1, bl + 2);
                        }
                    }

                    // ---- epilogue: gate exchange + cell update ----
                    const int p4 = lane & 3;
                    const int odd = p4 & 1;
                    #pragma unroll
                    for (int r = 0; r < 2; r++) {
                        if (r == 1 && !act1) break;
                        int mt = r ? mt1 : mt0;
                        #pragma unroll
                        for (int q = 0; q < 2; q++) {
                            float* d = acc[r][q];
                            float v0 = odd ? d[0] : d[2];
                            float v1 = odd ? d[1] : d[3];
                            float r0 = __shfl_xor_sync(0xffffffffu, v0, 1);
                            float r1 = __shfl_xor_sync(0xffffffffu, v1, 1);
                            float gi, gf, gg, go;
                            int row;
                            if (!odd) { gi = d[0]; gf = d[1]; gg = r0; go = r1; row = mt * 16 + (lane >> 2); }
                            else      { gi = r0;   gf = r1;   gg = d[2]; go = d[3]; row = mt * 16 + (lane >> 2) + 8; }
                            int j = nc * 8 + nh * 4 + q * 2 + (p4 >> 1);
                            if (row < cnt) {
                                int n = sActive[row];
                                float iv = sigm(gi + sBias[j]);
                                float fv = sigm(gf + sBias[128 + j]);
                                float gv = tanh_apx(gg + sBias[256 + j]);
                                float ov = sigm(go + sBias[384 + j]);
                                size_t cix = (size_t)j * N_NODES + base + n;
                                float cn = fmaf(fv, g_C[cix], iv * gv);
                                float hn = ov * tanh_apx(cn);
                                g_C[cix] = cn;
                                unsigned short hb, lb;
                                bf16_split(hn, hb, lb);
                                ((unsigned short*)(smem + SM_HH))[n * 128 + j] = hb;
                                ((unsigned short*)(smem + SM_HL))[n * 128 + j] = lb;
                            }
                        }
                    }
                }
                __syncthreads();
            }
        }

        // ---- out projection for active nodes ----
        for (int a = wid; a < cnt; a += 8) {
            int n = sActive[a];
            float o0 = 0.f, o1 = 0.f, o2 = 0.f, o3 = 0.f, o4 = 0.f;
            #pragma unroll
            for (int q = 0; q < 2; q++) {
                int u = lane + 32 * q;
                uint32_t hw = ((uint32_t*)(smem + SM_HH))[n * 64 + u];
                uint32_t lw = ((uint32_t*)(smem + SM_HL))[n * 64 + u];
                float hv0 = __bfloat162float(__ushort_as_bfloat16((unsigned short)(hw & 0xffff)))
                          + __bfloat162float(__ushort_as_bfloat16((unsigned short)(lw & 0xffff)));
                float hv1 = __bfloat162float(__ushort_as_bfloat16((unsigned short)(hw >> 16)))
                          + __bfloat162float(__ushort_as_bfloat16((unsigned short)(lw >> 16)));
                const float* w0 = sWout + (2 * u) * 5;
                o0 = fmaf(hv0, w0[0], fmaf(hv1, w0[5], o0));
                o1 = fmaf(hv0, w0[1], fmaf(hv1, w0[6], o1));
                o2 = fmaf(hv0, w0[2], fmaf(hv1, w0[7], o2));
                o3 = fmaf(hv0, w0[3], fmaf(hv1, w0[8], o3));
                o4 = fmaf(hv0, w0[4], fmaf(hv1, w0[9], o4));
            }
            #pragma unroll
            for (int off = 16; off > 0; off >>= 1) {
                o0 += __shfl_down_sync(0xffffffffu, o0, off);
                o1 += __shfl_down_sync(0xffffffffu, o1, off);
                o2 += __shfl_down_sync(0xffffffffu, o2, off);
                o3 += __shfl_down_sync(0xffffffffu, o3, off);
                o4 += __shfl_down_sync(0xffffffffu, o4, off);
            }
            if (lane == 0) {
                float* op = out + ((size_t)t * N_NODES + base + n) * 5;
                op[0] = o0 + sBout[0];
                op[1] = o1 + sBout[1];
                op[2] = o2 + sBout[2];
                op[3] = o3 + sBout[3];
                op[4] = o4 + sBout[4];
            }
        }
        if (tid < TILE_N && !sMask[tid]) {
            float* op = out + ((size_t)t * N_NODES + base + tid) * 5;
            op[0] = 0.f; op[1] = 0.f; op[2] = 0.f; op[3] = 0.f; op[4] = 0.f;
        }
        __syncthreads();
    }

    // ---- final h, c ----
    for (int idx = tid; idx < TILE_N * 64; idx += NTHREADS) {
        int n = idx >> 6, q = idx & 63;
        uint32_t hw = ((uint32_t*)(smem + SM_HH))[n * 64 + q];
        uint32_t lw = ((uint32_t*)(smem + SM_HL))[n * 64 + q];
        float2 hv;
        hv.x = __bfloat162float(__ushort_as_bfloat16((unsigned short)(hw & 0xffff)))
             + __bfloat162float(__ushort_as_bfloat16((unsigned short)(lw & 0xffff)));
        hv.y = __bfloat162float(__ushort_as_bfloat16((unsigned short)(hw >> 16)))
             + __bfloat162float(__ushort_as_bfloat16((unsigned short)(lw >> 16)));
        ((float2*)hfin)[(size_t)(base + n) * 64 + q] = hv;
    }
    for (int idx = tid; idx < TILE_N * DH; idx += NTHREADS) {
        int j = idx >> 7, n = idx & 127;
        cfin[(size_t)(base + n) * DH + j] = g_C[(size_t)j * N_NODES + base + n];
    }
}

extern "C" void kernel_launch(void* const* d_in, const int* in_sizes, int n_in,
                              void* d_out, int out_size) {
    const float* nodes = (const float*)d_in[0];
    const int* mask    = (const int*)d_in[1];     // bool -> int32
    const float* h0    = (const float*)d_in[2];
    const float* c0    = (const float*)d_in[3];
    const float* We    = (const float*)d_in[4];
    const float* be    = (const float*)d_in[5];
    const float* Wih   = (const float*)d_in[6];
    const float* bih   = (const float*)d_in[7];
    const float* Whh   = (const float*)d_in[8];
    const float* bhh   = (const float*)d_in[9];
    const float* Wout  = (const float*)d_in[10];
    const float* bout  = (const float*)d_in[11];

    float* out  = (float*)d_out;                            // [20, 32768, 5]
    float* hfin = out + (size_t)T_STEPS * N_NODES * 5;      // [32768, 128]
    float* cfin = hfin + (size_t)N_NODES * DH;              // [32768, 128]

    prep_kernel<<<(512 * K_TOT + 255) / 256, 256>>>(Wih, Whh);

    cudaFuncSetAttribute(vlstm_mma, cudaFuncAttributeMaxDynamicSharedMemorySize, SMEM_TOTAL);
    vlstm_mma<<<NBLOCKS, NTHREADS, SMEM_TOTAL>>>(
        nodes, mask, h0, c0, We, be, bih, bhh, Wout, bout, out, hfin, cfin);
}

// round 7
// speedup vs baseline: 2.0164x; 1.4956x over previous
#include <cuda_runtime.h>
#include <cuda_bf16.h>
#include <cstdint>

#define T_STEPS 20
#define N_NODES 32768
#define TILE_N  128
#define DH      128
#define K_TOT   192
#define NBLOCKS (N_NODES / TILE_N)   // 256
#define NTHREADS 384
#define NW      12                   // MMA warps
#define NCHUNKS 16                   // 512 interleaved gate cols in chunks of 32
#define XPITCH  400                  // bytes per X/W row (200 bf16, 16B-aligned rows)
#define WCHUNK  12800                // 32 rows * 400B
#define CPITCH  130

// SMEM byte offsets
#define SM_XH 0                      // X hi: 128 x 400
#define SM_XL 51200                  // X lo
#define SM_WB 102400                 // 2 bufs x (hi 12800 + lo 12800)
#define SM_C  153600                 // c: 128 j x 130 n fp32 (66560B)
#define SM_F  220160                 // float region
#define SMEM_TOTAL 227624

// ---- static device scratch ----
__device__ unsigned short g_WH[NCHUNKS * 32 * 200];   // bf16 bits [chunk][row][200]
__device__ unsigned short g_WL[NCHUNKS * 32 * 200];
__device__ uint32_t g_H[(size_t)N_NODES * DH];        // h packed: hi | lo<<16

// prep: W'[n'=j*4+g][k] = Wfull[k][g*128+j], bf16 hi/lo, pitch 200
__global__ void prep_kernel(const float* __restrict__ Wih, const float* __restrict__ Whh) {
    int idx = blockIdx.x * blockDim.x + threadIdx.x;
    if (idx >= 512 * K_TOT) return;
    int np = idx / K_TOT;
    int k  = idx % K_TOT;
    int j = np >> 2, g = np & 3;
    int col = g * 128 + j;
    float w = (k < 64) ? Wih[k * 512 + col] : Whh[(k - 64) * 512 + col];
    __nv_bfloat16 hi = __float2bfloat16(w);
    __nv_bfloat16 lo = __float2bfloat16(w - __bfloat162float(hi));
    int off = (np >> 5) * 6400 + (np & 31) * 200 + k;
    g_WH[off] = __bfloat16_as_ushort(hi);
    g_WL[off] = __bfloat16_as_ushort(lo);
}

// ---- PTX helpers (portable ISA only) ----
__device__ __forceinline__ uint32_t smem_u32(const void* p) {
    uint32_t a;
    asm("{ .reg .u64 t; cvta.to.shared.u64 t, %1; cvt.u32.u64 %0, t; }" : "=r"(a) : "l"(p));
    return a;
}
__device__ __forceinline__ void ldsm4(uint32_t& r0, uint32_t& r1, uint32_t& r2, uint32_t& r3, uint32_t addr) {
    asm volatile("ldmatrix.sync.aligned.m8n8.x4.shared.b16 {%0,%1,%2,%3}, [%4];"
                 : "=r"(r0), "=r"(r1), "=r"(r2), "=r"(r3) : "r"(addr));
}
__device__ __forceinline__ void mma16816(float* d, const uint32_t* a, const uint32_t* b) {
    asm volatile("mma.sync.aligned.m16n8k16.row.col.f32.bf16.bf16.f32 "
                 "{%0,%1,%2,%3},{%4,%5,%6,%7},{%8,%9},{%0,%1,%2,%3};"
                 : "+f"(d[0]), "+f"(d[1]), "+f"(d[2]), "+f"(d[3])
                 : "r"(a[0]), "r"(a[1]), "r"(a[2]), "r"(a[3]), "r"(b[0]), "r"(b[1]));
}
__device__ __forceinline__ void cpasync16(uint32_t dst, const void* src) {
    asm volatile("cp.async.cg.shared.global [%0], [%1], 16;" :: "r"(dst), "l"(src) : "memory");
}
#define CP_COMMIT() asm volatile("cp.async.commit_group;" ::: "memory")
#define CP_WAIT(N)  asm volatile("cp.async.wait_group %0;" :: "n"(N) : "memory")

__device__ __forceinline__ float tanh_apx(float x) {
    float y;
    asm("tanh.approx.f32 %0, %1;" : "=f"(y) : "f"(x));
    return y;
}
__device__ __forceinline__ float sigm(float x) { return fmaf(0.5f, tanh_apx(0.5f * x), 0.5f); }
__device__ __forceinline__ void bf16_split(float v, unsigned short& hi, unsigned short& lo) {
    __nv_bfloat16 h = __float2bfloat16(v);
    hi = __bfloat16_as_ushort(h);
    lo = __bfloat16_as_ushort(__float2bfloat16(v - __bfloat162float(h)));
}
__device__ __forceinline__ float unpackH(uint32_t w) {
    return __bfloat162float(__ushort_as_bfloat16((unsigned short)(w & 0xffff)))
         + __bfloat162float(__ushort_as_bfloat16((unsigned short)(w >> 16)));
}

__global__ __launch_bounds__(NTHREADS, 1)
void vlstm_mma(const float* __restrict__ nodes,
               const int* __restrict__ mask,
               const float* __restrict__ h0,
               const float* __restrict__ c0,
               const float* __restrict__ We,
               const float* __restrict__ be,
               const float* __restrict__ bih,
               const float* __restrict__ bhh,
               const float* __restrict__ Wout,
               const float* __restrict__ bout,
               float* __restrict__ out,
               float* __restrict__ hfin,
               float* __restrict__ cfin) {
    extern __shared__ char smem[];
    float* sc    = (float*)(smem + SM_C);   // [j][CPITCH]
    float* sBias = (float*)(smem + SM_F);   // 512
    float* sWe   = sBias + 512;             // 128
    float* sBe   = sWe + 128;               // 64
    float* sWout = sBe + 64;                // 640
    float* sBout = sWout + 640;             // 8
    float* sXY   = sBout + 8;               // 256
    int* sActive = (int*)(sXY + 256);       // 128
    int* sMask   = sActive + 128;           // 128
    int* sCnt    = sMask + 128;             // 2

    const int tid  = threadIdx.x;
    const int wid  = tid >> 5, lane = tid & 31;
    const int base = blockIdx.x * TILE_N;
    const uint32_t sbase = smem_u32(smem);

    // stage constants
    for (int i = tid; i < 512; i += NTHREADS) sBias[i] = bih[i] + bhh[i];
    for (int i = tid; i < 128; i += NTHREADS) sWe[i] = We[i];
    for (int i = tid; i < 64;  i += NTHREADS) sBe[i] = be[i];
    for (int i = tid; i < 640; i += NTHREADS) sWout[i] = Wout[i];
    if (tid < 5) sBout[tid] = bout[tid];

    // zero X buffers (padded-row hygiene)
    for (int i = tid; i < 12800; i += NTHREADS) {
        ((uint32_t*)(smem + SM_XH))[i] = 0;
        ((uint32_t*)(smem + SM_XL))[i] = 0;
    }
    // h0 -> g_H packed; c0 -> sc transposed
    for (int idx = tid; idx < TILE_N * DH; idx += NTHREADS) {
        int n = idx >> 7, j = idx & 127;
        unsigned short hb, lb;
        bf16_split(h0[(size_t)(base + n) * DH + j], hb, lb);
        g_H[(size_t)(base + n) * DH + j] = (uint32_t)hb | ((uint32_t)lb << 16);
        sc[j * CPITCH + n] = c0[(size_t)(base + n) * DH + j];
    }
    __syncthreads();

    // A-operand lane addressing (row within 16-row tile, 16B col offset)
    const uint32_t aoff = (uint32_t)((lane & 7) + ((lane >> 3) & 1) * 8) * XPITCH
                        + (uint32_t)(lane >> 4) * 16;
    // B-operand lane addressing within a 16-row half (nh row base added per task)
    const uint32_t boff = (uint32_t)((lane & 7) + ((lane >> 4) & 1) * 8) * XPITCH
                        + (uint32_t)((lane >> 3) & 1) * 16;
    const int p4 = lane & 3, odd = p4 & 1;

    for (int t = 0; t < T_STEPS; t++) {
        // ---- compaction (warp 0) ----
        if (tid < 32) {
            int cnt = 0;
            #pragma unroll
            for (int g2 = 0; g2 < 4; g2++) {
                int m = mask[(size_t)t * N_NODES + base + g2 * 32 + tid] != 0;
                sMask[g2 * 32 + tid] = m;
                unsigned b = __ballot_sync(0xffffffffu, m);
                if (m) sActive[cnt + __popc(b & ((1u << tid) - 1u))] = g2 * 32 + tid;
                cnt += __popc(b);
            }
            int pad = (cnt + 15) & ~15;
            __syncwarp();
            int dup = (cnt > 0) ? sActive[0] : 0;
            for (int p = cnt + tid; p < pad; p += 32) sActive[p] = dup;
            if (tid == 0) { sCnt[0] = cnt; sCnt[1] = pad; }
        }
        __syncthreads();
        const int cnt = sCnt[0];
        const int pad = sCnt[1];

        if (pad > 0) {
            // ---- stage xy, gather h (g_H -> X rows), prefetch chunk 0 ----
            if (tid < pad) {
                int n = base + sActive[tid];
                float2 xy = ((const float2*)nodes)[(size_t)t * N_NODES + n];
                sXY[2 * tid] = xy.x;
                sXY[2 * tid + 1] = xy.y;
            }
            for (int idx = tid; idx < pad * DH; idx += NTHREADS) {
                int a = idx >> 7, j = idx & 127;
                uint32_t w = g_H[(size_t)(base + sActive[a]) * DH + j];
                *(unsigned short*)(smem + SM_XH + a * XPITCH + 128 + 2 * j) = (unsigned short)(w & 0xffff);
                *(unsigned short*)(smem + SM_XL + a * XPITCH + 128 + 2 * j) = (unsigned short)(w >> 16);
            }
            for (int i = tid * 16; i < WCHUNK; i += NTHREADS * 16) {
                cpasync16(sbase + SM_WB + i, (const char*)g_WH + i);
                cpasync16(sbase + SM_WB + WCHUNK + i, (const char*)g_WL + i);
            }
            CP_COMMIT();
            __syncthreads();

            // ---- emb rows (X cols 0..63) ----
            for (int idx = tid; idx < pad * 64; idx += NTHREADS) {
                int a = idx >> 6, k = idx & 63;
                float e = fmaxf(fmaf(sXY[2 * a], sWe[k],
                                fmaf(sXY[2 * a + 1], sWe[64 + k], sBe[k])), 0.0f);
                unsigned short hi, lo;
                bf16_split(e, hi, lo);
                *(unsigned short*)(smem + SM_XH + a * XPITCH + 2 * k) = hi;
                *(unsigned short*)(smem + SM_XL + a * XPITCH + 2 * k) = lo;
            }

            const int ntasks = (pad >> 4) * 2;   // (16-row pair) x (n-half)

            // ---- chunk pipeline ----
            for (int nc = 0; nc < NCHUNKS; nc++) {
                int buf = nc & 1;
                if (nc + 1 < NCHUNKS) {
                    int nbuf = (nc + 1) & 1;
                    const char* srcH = (const char*)g_WH + (nc + 1) * WCHUNK;
                    const char* srcL = (const char*)g_WL + (nc + 1) * WCHUNK;
                    uint32_t dstH = sbase + SM_WB + nbuf * 2 * WCHUNK;
                    for (int i = tid * 16; i < WCHUNK; i += NTHREADS * 16) {
                        cpasync16(dstH + i, srcH + i);
                        cpasync16(dstH + WCHUNK + i, srcL + i);
                    }
                    CP_COMMIT();
                    CP_WAIT(1);
                } else {
                    CP_WAIT(0);
                }
                __syncthreads();

                for (int task = wid; task < ntasks; task += NW) {
                    const int mt = task >> 1;
                    const int nh = task & 1;
                    float acc[2][4];
                    #pragma unroll
                    for (int q = 0; q < 2; q++)
                        #pragma unroll
                        for (int z = 0; z < 4; z++) acc[q][z] = 0.0f;

                    const uint32_t xh = sbase + SM_XH + (uint32_t)mt * 16 * XPITCH + aoff;
                    const uint32_t xl = sbase + SM_XL + (uint32_t)mt * 16 * XPITCH + aoff;
                    const uint32_t wb = sbase + SM_WB + (uint32_t)buf * 2 * WCHUNK
                                      + (uint32_t)nh * 16 * XPITCH + boff;

                    #pragma unroll 4
                    for (int kk = 0; kk < 12; kk++) {
                        uint32_t kb = kk * 32;
                        uint32_t bh[4], bl[4], ah[4], al[4];
                        ldsm4(bh[0], bh[1], bh[2], bh[3], wb + kb);
                        ldsm4(bl[0], bl[1], bl[2], bl[3], wb + WCHUNK + kb);
                        ldsm4(ah[0], ah[1], ah[2], ah[3], xh + kb);
                        ldsm4(al[0], al[1], al[2], al[3], xl + kb);
                        mma16816(acc[0], ah, bh + 0);
                        mma16816(acc[1], ah, bh + 2);
                        mma16816(acc[0], al, bh + 0);
                        mma16816(acc[1], al, bh + 2);
                        mma16816(acc[0], ah, bl + 0);
                        mma16816(acc[1], ah, bl + 2);
                    }

                    // ---- epilogue: gate exchange + cell update (c in SMEM) ----
                    #pragma unroll
                    for (int q = 0; q < 2; q++) {
                        float* d = acc[q];
                        float v0 = odd ? d[0] : d[2];
                        float v1 = odd ? d[1] : d[3];
                        float r0 = __shfl_xor_sync(0xffffffffu, v0, 1);
                        float r1 = __shfl_xor_sync(0xffffffffu, v1, 1);
                        float gi, gf, gg, go;
                        int row;
                        if (!odd) { gi = d[0]; gf = d[1]; gg = r0; go = r1; row = mt * 16 + (lane >> 2); }
                        else      { gi = r0;   gf = r1;   gg = d[2]; go = d[3]; row = mt * 16 + (lane >> 2) + 8; }
                        int j = nc * 8 + nh * 4 + q * 2 + (p4 >> 1);
                        if (row < cnt) {
                            int n = sActive[row];
                            float iv = sigm(gi + sBias[j]);
                            float fv = sigm(gf + sBias[128 + j]);
                            float gv = tanh_apx(gg + sBias[256 + j]);
                            float ov = sigm(go + sBias[384 + j]);
                            float cn = fmaf(fv, sc[j * CPITCH + n], iv * gv);
                            float hn = ov * tanh_apx(cn);
                            sc[j * CPITCH + n] = cn;
                            unsigned short hb, lb;
                            bf16_split(hn, hb, lb);
                            g_H[(size_t)(base + n) * DH + j] = (uint32_t)hb | ((uint32_t)lb << 16);
                        }
                    }
                }
                __syncthreads();
            }
        }

        // ---- out projection for active nodes (h from g_H, L2/L1) ----
        for (int a = wid; a < cnt; a += NW) {
            int n = sActive[a];
            const uint32_t* hp = g_H + (size_t)(base + n) * DH;
            float o0 = 0.f, o1 = 0.f, o2 = 0.f, o3 = 0.f, o4 = 0.f;
            #pragma unroll
            for (int q = 0; q < 4; q++) {
                int u = lane + 32 * q;
                float hv = unpackH(hp[u]);
                const float* w0 = sWout + u * 5;
                o0 = fmaf(hv, w0[0], o0);
                o1 = fmaf(hv, w0[1], o1);
                o2 = fmaf(hv, w0[2], o2);
                o3 = fmaf(hv, w0[3], o3);
                o4 = fmaf(hv, w0[4], o4);
            }
            #pragma unroll
            for (int off = 16; off > 0; off >>= 1) {
                o0 += __shfl_down_sync(0xffffffffu, o0, off);
                o1 += __shfl_down_sync(0xffffffffu, o1, off);
                o2 += __shfl_down_sync(0xffffffffu, o2, off);
                o3 += __shfl_down_sync(0xffffffffu, o3, off);
                o4 += __shfl_down_sync(0xffffffffu, o4, off);
            }
            if (lane == 0) {
                float* op = out + ((size_t)t * N_NODES + base + n) * 5;
                op[0] = o0 + sBout[0];
                op[1] = o1 + sBout[1];
                op[2] = o2 + sBout[2];
                op[3] = o3 + sBout[3];
                op[4] = o4 + sBout[4];
            }
        }
        if (tid < TILE_N && !sMask[tid]) {
            float* op = out + ((size_t)t * N_NODES + base + tid) * 5;
            op[0] = 0.f; op[1] = 0.f; op[2] = 0.f; op[3] = 0.f; op[4] = 0.f;
        }
        __syncthreads();
    }

    // ---- final h, c ----
    for (int idx = tid; idx < TILE_N * DH; idx += NTHREADS) {
        int n = idx >> 7, j = idx & 127;
        hfin[(size_t)(base + n) * DH + j] = unpackH(g_H[(size_t)(base + n) * DH + j]);
        cfin[(size_t)(base + n) * DH + j] = sc[j * CPITCH + n];
    }
}

extern "C" void kernel_launch(void* const* d_in, const int* in_sizes, int n_in,
                              void* d_out, int out_size) {
    const float* nodes = (const float*)d_in[0];
    const int* mask    = (const int*)d_in[1];     // bool -> int32
    const float* h0    = (const float*)d_in[2];
    const float* c0    = (const float*)d_in[3];
    const float* We    = (const float*)d_in[4];
    const float* be    = (const float*)d_in[5];
    const float* Wih   = (const float*)d_in[6];
    const float* bih   = (const float*)d_in[7];
    const float* Whh   = (const float*)d_in[8];
    const float* bhh   = (const float*)d_in[9];
    const float* Wout  = (const float*)d_in[10];
    const float* bout  = (const float*)d_in[11];

    float* out  = (float*)d_out;                            // [20, 32768, 5]
    float* hfin = out + (size_t)T_STEPS * N_NODES * 5;      // [32768, 128]
    float* cfin = hfin + (size_t)N_NODES * DH;              // [32768, 128]

    prep_kernel<<<(512 * K_TOT + 255) / 256, 256>>>(Wih, Whh);

    cudaFuncSetAttribute(vlstm_mma, cudaFuncAttributeMaxDynamicSharedMemorySize, SMEM_TOTAL);
    vlstm_mma<<<NBLOCKS, NTHREADS, SMEM_TOTAL>>>(
        nodes, mask, h0, c0, We, be, bih, bhh, Wout, bout, out, hfin, cfin);
}

// round 8
// speedup vs baseline: 2.1242x; 1.0534x over previous
#include <cuda_runtime.h>
#include <cuda_bf16.h>
#include <cstdint>

#define T_STEPS 20
#define N_NODES 32768
#define TILE_N  128
#define DH      128
#define K_TOT   192
#define NBLOCKS (N_NODES / TILE_N)   // 256
#define NTHREADS 384
#define NW      12                   // MMA warps
#define NCHUNKS 16                   // 512 interleaved gate cols in chunks of 32
#define XPITCH  400                  // bytes per X/W row (200 bf16, 16B-aligned rows)
#define WCHUNK  12800                // 32 rows * 400B
#define CPITCH  129

// SMEM byte offsets
#define SM_XH 0                      // X hi: 128 x 400
#define SM_XL 51200                  // X lo
#define SM_WB 102400                 // 2 bufs x (hi 12800 + lo 12800)
#define SM_C  153600                 // c: 128 j x 129 n fp32 (66048B)
#define SM_F  219648                 // float region
#define SMEM_TOTAL 232240

// ---- static device scratch ----
__device__ unsigned short g_WH[NCHUNKS * 32 * 200];   // bf16 bits [chunk][row][200]
__device__ unsigned short g_WL[NCHUNKS * 32 * 200];
__device__ uint32_t g_H[(size_t)N_NODES * DH];        // h packed: hi | lo<<16

// prep: W'[n'=j*4+g][k] = Wfull[k][g*128+j], bf16 hi/lo, pitch 200
__global__ void prep_kernel(const float* __restrict__ Wih, const float* __restrict__ Whh) {
    int idx = blockIdx.x * blockDim.x + threadIdx.x;
    if (idx >= 512 * K_TOT) return;
    int np = idx / K_TOT;
    int k  = idx % K_TOT;
    int j = np >> 2, g = np & 3;
    int col = g * 128 + j;
    float w = (k < 64) ? Wih[k * 512 + col] : Whh[(k - 64) * 512 + col];
    __nv_bfloat16 hi = __float2bfloat16(w);
    __nv_bfloat16 lo = __float2bfloat16(w - __bfloat162float(hi));
    int off = (np >> 5) * 6400 + (np & 31) * 200 + k;
    g_WH[off] = __bfloat16_as_ushort(hi);
    g_WL[off] = __bfloat16_as_ushort(lo);
}

// ---- PTX helpers (portable ISA only) ----
__device__ __forceinline__ uint32_t smem_u32(const void* p) {
    uint32_t a;
    asm("{ .reg .u64 t; cvta.to.shared.u64 t, %1; cvt.u32.u64 %0, t; }" : "=r"(a) : "l"(p));
    return a;
}
__device__ __forceinline__ void ldsm4(uint32_t& r0, uint32_t& r1, uint32_t& r2, uint32_t& r3, uint32_t addr) {
    asm volatile("ldmatrix.sync.aligned.m8n8.x4.shared.b16 {%0,%1,%2,%3}, [%4];"
                 : "=r"(r0), "=r"(r1), "=r"(r2), "=r"(r3) : "r"(addr));
}
__device__ __forceinline__ void mma16816(float* d, const uint32_t* a, const uint32_t* b) {
    asm volatile("mma.sync.aligned.m16n8k16.row.col.f32.bf16.bf16.f32 "
                 "{%0,%1,%2,%3},{%4,%5,%6,%7},{%8,%9},{%0,%1,%2,%3};"
                 : "+f"(d[0]), "+f"(d[1]), "+f"(d[2]), "+f"(d[3])
                 : "r"(a[0]), "r"(a[1]), "r"(a[2]), "r"(a[3]), "r"(b[0]), "r"(b[1]));
}
__device__ __forceinline__ void cpasync16(uint32_t dst, const void* src) {
    asm volatile("cp.async.cg.shared.global [%0], [%1], 16;" :: "r"(dst), "l"(src) : "memory");
}
#define CP_COMMIT() asm volatile("cp.async.commit_group;" ::: "memory")
#define CP_WAIT(N)  asm volatile("cp.async.wait_group %0;" :: "n"(N) : "memory")

__device__ __forceinline__ float tanh_apx(float x) {
    float y;
    asm("tanh.approx.f32 %0, %1;" : "=f"(y) : "f"(x));
    return y;
}
__device__ __forceinline__ float sigm(float x) { return fmaf(0.5f, tanh_apx(0.5f * x), 0.5f); }
__device__ __forceinline__ void bf16_split(float v, unsigned short& hi, unsigned short& lo) {
    __nv_bfloat16 h = __float2bfloat16(v);
    hi = __bfloat16_as_ushort(h);
    lo = __bfloat16_as_ushort(__float2bfloat16(v - __bfloat162float(h)));
}
__device__ __forceinline__ float unpackH(uint32_t w) {
    return __bfloat162float(__ushort_as_bfloat16((unsigned short)(w & 0xffff)))
         + __bfloat162float(__ushort_as_bfloat16((unsigned short)(w >> 16)));
}

__global__ __launch_bounds__(NTHREADS, 1)
void vlstm_mma(const float* __restrict__ nodes,
               const int* __restrict__ mask,
               const float* __restrict__ h0,
               const float* __restrict__ c0,
               const float* __restrict__ We,
               const float* __restrict__ be,
               const float* __restrict__ bih,
               const float* __restrict__ bhh,
               const float* __restrict__ Wout,
               const float* __restrict__ bout,
               float* __restrict__ out,
               float* __restrict__ hfin,
               float* __restrict__ cfin) {
    extern __shared__ char smem[];
    float* sc    = (float*)(smem + SM_C);   // [j][CPITCH]
    float* sBias = (float*)(smem + SM_F);   // 512
    float* sWe   = sBias + 512;             // 128
    float* sBe   = sWe + 128;               // 64
    float* sWout = sBe + 64;                // 640
    float* sBout = sWout + 640;             // 8
    float* sXY   = sBout + 8;               // 256
    float* sOutP = sXY + 256;               // 128 rows x 2 nh x 5
    int* sActive = (int*)(sOutP + 1280);    // 128
    int* sMask   = sActive + 128;           // 128
    int* sCnt    = sMask + 128;             // 2

    const int tid  = threadIdx.x;
    const int wid  = tid >> 5, lane = tid & 31;
    const int base = blockIdx.x * TILE_N;
    const uint32_t sbase = smem_u32(smem);

    // stage constants
    for (int i = tid; i < 512; i += NTHREADS) sBias[i] = bih[i] + bhh[i];
    for (int i = tid; i < 128; i += NTHREADS) sWe[i] = We[i];
    for (int i = tid; i < 64;  i += NTHREADS) sBe[i] = be[i];
    for (int i = tid; i < 640; i += NTHREADS) sWout[i] = Wout[i];
    if (tid < 5) sBout[tid] = bout[tid];

    // zero X buffers (padded-row hygiene)
    for (int i = tid; i < 12800; i += NTHREADS) {
        ((uint32_t*)(smem + SM_XH))[i] = 0;
        ((uint32_t*)(smem + SM_XL))[i] = 0;
    }
    // h0 -> g_H packed; c0 -> sc transposed
    for (int idx = tid; idx < TILE_N * DH; idx += NTHREADS) {
        int n = idx >> 7, j = idx & 127;
        unsigned short hb, lb;
        bf16_split(h0[(size_t)(base + n) * DH + j], hb, lb);
        g_H[(size_t)(base + n) * DH + j] = (uint32_t)hb | ((uint32_t)lb << 16);
        sc[j * CPITCH + n] = c0[(size_t)(base + n) * DH + j];
    }
    __syncthreads();

    // A-operand lane addressing (row within 16-row tile, 16B col offset)
    const uint32_t aoff = (uint32_t)((lane & 7) + ((lane >> 3) & 1) * 8) * XPITCH
                        + (uint32_t)(lane >> 4) * 16;
    // B-operand lane addressing within a 16-row half (nh row base added per task)
    const uint32_t boff = (uint32_t)((lane & 7) + ((lane >> 4) & 1) * 8) * XPITCH
                        + (uint32_t)((lane >> 3) & 1) * 16;
    const int p4 = lane & 3, odd = p4 & 1;

    for (int t = 0; t < T_STEPS; t++) {
        // ---- compaction (warp 0) ----
        if (tid < 32) {
            int cnt = 0;
            #pragma unroll
            for (int g2 = 0; g2 < 4; g2++) {
                int m = mask[(size_t)t * N_NODES + base + g2 * 32 + tid] != 0;
                sMask[g2 * 32 + tid] = m;
                unsigned b = __ballot_sync(0xffffffffu, m);
                if (m) sActive[cnt + __popc(b & ((1u << tid) - 1u))] = g2 * 32 + tid;
                cnt += __popc(b);
            }
            int pad = (cnt + 15) & ~15;
            __syncwarp();
            int dup = (cnt > 0) ? sActive[0] : 0;
            for (int p = cnt + tid; p < pad; p += 32) sActive[p] = dup;
            if (tid == 0) { sCnt[0] = cnt; sCnt[1] = pad; }
        }
        __syncthreads();
        const int cnt = sCnt[0];
        const int pad = sCnt[1];

        if (pad > 0) {
            // ---- stage xy, gather h (g_H -> X rows), prefetch chunk 0 ----
            if (tid < pad) {
                int n = base + sActive[tid];
                float2 xy = ((const float2*)nodes)[(size_t)t * N_NODES + n];
                sXY[2 * tid] = xy.x;
                sXY[2 * tid + 1] = xy.y;
            }
            for (int idx = tid; idx < pad * DH; idx += NTHREADS) {
                int a = idx >> 7, j = idx & 127;
                uint32_t w = g_H[(size_t)(base + sActive[a]) * DH + j];
                *(unsigned short*)(smem + SM_XH + a * XPITCH + 128 + 2 * j) = (unsigned short)(w & 0xffff);
                *(unsigned short*)(smem + SM_XL + a * XPITCH + 128 + 2 * j) = (unsigned short)(w >> 16);
            }
            for (int i = tid * 16; i < WCHUNK; i += NTHREADS * 16) {
                cpasync16(sbase + SM_WB + i, (const char*)g_WH + i);
                cpasync16(sbase + SM_WB + WCHUNK + i, (const char*)g_WL + i);
            }
            CP_COMMIT();
            __syncthreads();

            // ---- emb rows (X cols 0..63); visible to tasks via chunk-0 sync ----
            for (int idx = tid; idx < pad * 64; idx += NTHREADS) {
                int a = idx >> 6, k = idx & 63;
                float e = fmaxf(fmaf(sXY[2 * a], sWe[k],
                                fmaf(sXY[2 * a + 1], sWe[64 + k], sBe[k])), 0.0f);
                unsigned short hi, lo;
                bf16_split(e, hi, lo);
                *(unsigned short*)(smem + SM_XH + a * XPITCH + 2 * k) = hi;
                *(unsigned short*)(smem + SM_XL + a * XPITCH + 2 * k) = lo;
            }

            const int ntasks = (pad >> 4) * 2;   // (16-row pair) x (n-half); <= 16
            float oaccA[5] = {0.f, 0.f, 0.f, 0.f, 0.f};
            float oaccB[5] = {0.f, 0.f, 0.f, 0.f, 0.f};

            // ---- chunk pipeline: ONE sync per chunk ----
            for (int nc = 0; nc < NCHUNKS; nc++) {
                int buf = nc & 1;
                CP_WAIT(0);
                __syncthreads();   // W[buf] visible; prev tasks done -> other buf free
                if (nc + 1 < NCHUNKS) {
                    const char* srcH = (const char*)g_WH + (nc + 1) * WCHUNK;
                    const char* srcL = (const char*)g_WL + (nc + 1) * WCHUNK;
                    uint32_t dstH = sbase + SM_WB + (buf ^ 1) * 2 * WCHUNK;
                    for (int i = tid * 16; i < WCHUNK; i += NTHREADS * 16) {
                        cpasync16(dstH + i, srcH + i);
                        cpasync16(dstH + WCHUNK + i, srcL + i);
                    }
                    CP_COMMIT();
                }

                for (int task = wid; task < ntasks; task += NW) {
                    const int mt = task >> 1;
                    const int nh = task & 1;
                    float* oacc = (task < NW) ? oaccA : oaccB;
                    float acc[2][4];
                    #pragma unroll
                    for (int q = 0; q < 2; q++)
                        #pragma unroll
                        for (int z = 0; z < 4; z++) acc[q][z] = 0.0f;

                    const uint32_t xh = sbase + SM_XH + (uint32_t)mt * 16 * XPITCH + aoff;
                    const uint32_t xl = sbase + SM_XL + (uint32_t)mt * 16 * XPITCH + aoff;
                    const uint32_t wb = sbase + SM_WB + (uint32_t)buf * 2 * WCHUNK
                                      + (uint32_t)nh * 16 * XPITCH + boff;

                    #pragma unroll 4
                    for (int kk = 0; kk < 12; kk++) {
                        uint32_t kb = kk * 32;
                        uint32_t bh[4], bl[4], ah[4], al[4];
                        ldsm4(bh[0], bh[1], bh[2], bh[3], wb + kb);
                        ldsm4(bl[0], bl[1], bl[2], bl[3], wb + WCHUNK + kb);
                        ldsm4(ah[0], ah[1], ah[2], ah[3], xh + kb);
                        ldsm4(al[0], al[1], al[2], al[3], xl + kb);
                        mma16816(acc[0], ah, bh + 0);
                        mma16816(acc[1], ah, bh + 2);
                        mma16816(acc[0], al, bh + 0);
                        mma16816(acc[1], al, bh + 2);
                        mma16816(acc[0], ah, bl + 0);
                        mma16816(acc[1], ah, bl + 2);
                    }

                    // ---- epilogue: gate exchange + cell update + fused out partials ----
                    #pragma unroll
                    for (int q = 0; q < 2; q++) {
                        float* d = acc[q];
                        float v0 = odd ? d[0] : d[2];
                        float v1 = odd ? d[1] : d[3];
                        float r0 = __shfl_xor_sync(0xffffffffu, v0, 1);
                        float r1 = __shfl_xor_sync(0xffffffffu, v1, 1);
                        float gi, gf, gg, go;
                        int row;
                        if (!odd) { gi = d[0]; gf = d[1]; gg = r0; go = r1; row = mt * 16 + (lane >> 2); }
                        else      { gi = r0;   gf = r1;   gg = d[2]; go = d[3]; row = mt * 16 + (lane >> 2) + 8; }
                        int j = nc * 8 + nh * 4 + q * 2 + (p4 >> 1);
                        if (row < cnt) {
                            int n = sActive[row];
                            float iv = sigm(gi + sBias[j]);
                            float fv = sigm(gf + sBias[128 + j]);
                            float gv = tanh_apx(gg + sBias[256 + j]);
                            float ov = sigm(go + sBias[384 + j]);
                            float cn = fmaf(fv, sc[j * CPITCH + n], iv * gv);
                            float hn = ov * tanh_apx(cn);
                            sc[j * CPITCH + n] = cn;
                            unsigned short hb, lb;
                            bf16_split(hn, hb, lb);
                            g_H[(size_t)(base + n) * DH + j] = (uint32_t)hb | ((uint32_t)lb << 16);
                            const float* w0 = sWout + j * 5;
                            oacc[0] = fmaf(hn, w0[0], oacc[0]);
                            oacc[1] = fmaf(hn, w0[1], oacc[1]);
                            oacc[2] = fmaf(hn, w0[2], oacc[2]);
                            oacc[3] = fmaf(hn, w0[3], oacc[3]);
                            oacc[4] = fmaf(hn, w0[4], oacc[4]);
                        }
                    }
                }
            }

            // ---- flush fused out partials: combine lane pairs (xor 2), store per (row, nh) ----
            #pragma unroll
            for (int slot = 0; slot < 2; slot++) {
                int task = wid + slot * NW;
                float* oa = slot ? oaccB : oaccA;
                if (task < ntasks) {
                    int mt = task >> 1, nh = task & 1;
                    float comb[5];
                    #pragma unroll
                    for (int z = 0; z < 5; z++)
                        comb[z] = oa[z] + __shfl_xor_sync(0xffffffffu, oa[z], 2);
                    int row = mt * 16 + (lane >> 2) + (lane & 1) * 8;
                    if ((lane & 3) < 2 && row < pad) {
                        float* s = sOutP + (row * 2 + nh) * 5;
                        s[0] = comb[0]; s[1] = comb[1]; s[2] = comb[2];
                        s[3] = comb[3]; s[4] = comb[4];
                    }
                }
            }
            __syncthreads();
        }

        // ---- write outputs ----
        if (tid < cnt) {
            int n = sActive[tid];
            float* pa = sOutP + tid * 10;
            float* op = out + ((size_t)t * N_NODES + base + n) * 5;
            op[0] = pa[0] + pa[5] + sBout[0];
            op[1] = pa[1] + pa[6] + sBout[1];
            op[2] = pa[2] + pa[7] + sBout[2];
            op[3] = pa[3] + pa[8] + sBout[3];
            op[4] = pa[4] + pa[9] + sBout[4];
        }
        if (tid < TILE_N && !sMask[tid]) {
            float* op = out + ((size_t)t * N_NODES + base + tid) * 5;
            op[0] = 0.f; op[1] = 0.f; op[2] = 0.f; op[3] = 0.f; op[4] = 0.f;
        }
        __syncthreads();
    }

    // ---- final h, c ----
    for (int idx = tid; idx < TILE_N * DH; idx += NTHREADS) {
        int n = idx >> 7, j = idx & 127;
        hfin[(size_t)(base + n) * DH + j] = unpackH(g_H[(size_t)(base + n) * DH + j]);
        cfin[(size_t)(base + n) * DH + j] = sc[j * CPITCH + n];
    }
}

extern "C" void kernel_launch(void* const* d_in, const int* in_sizes, int n_in,
                              void* d_out, int out_size) {
    const float* nodes = (const float*)d_in[0];
    const int* mask    = (const int*)d_in[1];     // bool -> int32
    const float* h0    = (const float*)d_in[2];
    const float* c0    = (const float*)d_in[3];
    const float* We    = (const float*)d_in[4];
    const float* be    = (const float*)d_in[5];
    const float* Wih   = (const float*)d_in[6];
    const float* bih   = (const float*)d_in[7];
    const float* Whh   = (const float*)d_in[8];
    const float* bhh   = (const float*)d_in[9];
    const float* Wout  = (const float*)d_in[10];
    const float* bout  = (const float*)d_in[11];

    float* out  = (float*)d_out;                            // [20, 32768, 5]
    float* hfin = out + (size_t)T_STEPS * N_NODES * 5;      // [32768, 128]
    float* cfin = hfin + (size_t)N_NODES * DH;              // [32768, 128]

    prep_kernel<<<(512 * K_TOT + 255) / 256, 256>>>(Wih, Whh);

    cudaFuncSetAttribute(vlstm_mma, cudaFuncAttributeMaxDynamicSharedMemorySize, SMEM_TOTAL);
    vlstm_mma<<<NBLOCKS, NTHREADS, SMEM_TOTAL>>>(
        nodes, mask, h0, c0, We, be, bih, bhh, Wout, bout, out, hfin, cfin);
}